// round 2
// baseline (speedup 1.0000x reference)
#include <cuda_runtime.h>

// Problem constants (fixed by dataset)
#define NN     40000      // nodes
#define NE     640000     // edges
#define DD     128        // feature dim
#define NBATCH 32         // graphs
#define IMGD   4096       // image feature dim
#define SCAN_BLOCKS 157   // ceil(NN/256)

// ---------------- scratch (static device globals; no allocations) -------------
__device__ float g_deg[NN];
__device__ float g_dis[NN];
__device__ int   g_hist[NN];
__device__ int   g_off[NN + 1];
__device__ int   g_cur[NN];
__device__ int   g_srcS[NE];
__device__ float g_wS[NE];
__device__ float g_Y[NN * DD];    // dis-scaled features (read-only during agg)
__device__ float g_T[NN * DD];    // aggregation result
__device__ float g_X3[NN * DD];   // conv3 output (pre-pool)
__device__ float g_q[NBATCH * IMGD];
__device__ float g_sums[NBATCH * DD];
__device__ float g_cnt[NBATCH];
__device__ int   g_bsum[SCAN_BLOCKS];

__device__ __forceinline__ void red_add(float* p, float v) {
    asm volatile("red.global.add.f32 [%0], %1;" :: "l"(p), "f"(v) : "memory");
}

// ---------------- init: deg=1 (self loop), hist=0, q=b_img, pool=0 ------------
__global__ void k_init(const float* __restrict__ b_img) {
    int i = blockIdx.x * blockDim.x + threadIdx.x;
    if (i < NBATCH * IMGD) g_q[i] = b_img[i & (IMGD - 1)];
    if (i < NN) { g_deg[i] = 1.0f; g_hist[i] = 0; }
    if (i < NBATCH * DD) g_sums[i] = 0.0f;
    if (i < NBATCH) g_cnt[i] = 0.0f;
}

// ---------------- degree + histogram ------------------------------------------
__global__ void k_deg_hist(const int* __restrict__ dst, const float* __restrict__ ew) {
    int e = blockIdx.x * blockDim.x + threadIdx.x;
    if (e < NE) {
        int d = dst[e];
        atomicAdd(&g_deg[d], ew[e]);
        atomicAdd(&g_hist[d], 1);
    }
}

// ---------------- 3-kernel exclusive scan of g_hist -> g_off ------------------
__global__ void k_scan1() {
    __shared__ int s[256];
    int tid = threadIdx.x;
    int i = blockIdx.x * 256 + tid;
    int v = (i < NN) ? g_hist[i] : 0;
    s[tid] = v; __syncthreads();
    for (int o = 1; o < 256; o <<= 1) {
        int t = (tid >= o) ? s[tid - o] : 0;
        __syncthreads();
        s[tid] += t;
        __syncthreads();
    }
    if (i < NN) g_off[i] = s[tid] - v;
    if (tid == 255) g_bsum[blockIdx.x] = s[255];
}
__global__ void k_scan2() {
    __shared__ int s[256];
    int tid = threadIdx.x;
    int v = (tid < SCAN_BLOCKS) ? g_bsum[tid] : 0;
    s[tid] = v; __syncthreads();
    for (int o = 1; o < 256; o <<= 1) {
        int t = (tid >= o) ? s[tid - o] : 0;
        __syncthreads();
        s[tid] += t;
        __syncthreads();
    }
    if (tid < SCAN_BLOCKS) g_bsum[tid] = s[tid] - v;
}
__global__ void k_scan3() {
    int i = blockIdx.x * 256 + threadIdx.x;
    if (i < NN) {
        int val = g_off[i] + g_bsum[blockIdx.x];
        g_off[i] = val;
        g_cur[i] = val;
    }
    if (i == 0) g_off[NN] = NE;
}

// ---------------- scatter edges into dst-sorted order -------------------------
__global__ void k_scatter(const int* __restrict__ src, const int* __restrict__ dst,
                          const float* __restrict__ ew) {
    int e = blockIdx.x * blockDim.x + threadIdx.x;
    if (e < NE) {
        int d = dst[e];
        int p = atomicAdd(&g_cur[d], 1);
        g_srcS[p] = src[e];
        g_wS[p] = ew[e];
    }
}

// ---------------- embedding gather + dis computation --------------------------
__global__ void k_gather(const int* __restrict__ ids, const float* __restrict__ emb) {
    int t = blockIdx.x * blockDim.x + threadIdx.x;
    int row = t >> 5, lane = t & 31;
    if (row >= NN) return;
    float ds = rsqrtf(g_deg[row]);
    if (lane == 0) g_dis[row] = ds;
    int id = ids[row];
    float4 v = ((const float4*)emb)[id * (DD / 4) + lane];
    v.x *= ds; v.y *= ds; v.z *= ds; v.w *= ds;
    ((float4*)g_Y)[row * (DD / 4) + lane] = v;
}

// ---------------- aggregation: T[d] = Y[d] + sum_e w_e * Y[src_e] -------------
// warp per destination node; pure gathers (no atomics), edges dst-sorted.
__global__ void k_agg() {
    int t = blockIdx.x * blockDim.x + threadIdx.x;
    int row = t >> 5, lane = t & 31;
    if (row >= NN) return;
    const float4* Y4 = (const float4*)g_Y;
    float4 acc = Y4[row * 32 + lane];     // self loop (w=1, already dis-scaled)
    int j = g_off[row], end = g_off[row + 1];
    for (; j + 4 <= end; j += 4) {
        int s0 = g_srcS[j], s1 = g_srcS[j + 1], s2 = g_srcS[j + 2], s3 = g_srcS[j + 3];
        float w0 = g_wS[j], w1 = g_wS[j + 1], w2 = g_wS[j + 2], w3 = g_wS[j + 3];
        float4 v0 = Y4[s0 * 32 + lane];
        float4 v1 = Y4[s1 * 32 + lane];
        float4 v2 = Y4[s2 * 32 + lane];
        float4 v3 = Y4[s3 * 32 + lane];
        acc.x = fmaf(w0, v0.x, acc.x); acc.y = fmaf(w0, v0.y, acc.y);
        acc.z = fmaf(w0, v0.z, acc.z); acc.w = fmaf(w0, v0.w, acc.w);
        acc.x = fmaf(w1, v1.x, acc.x); acc.y = fmaf(w1, v1.y, acc.y);
        acc.z = fmaf(w1, v1.z, acc.z); acc.w = fmaf(w1, v1.w, acc.w);
        acc.x = fmaf(w2, v2.x, acc.x); acc.y = fmaf(w2, v2.y, acc.y);
        acc.z = fmaf(w2, v2.z, acc.z); acc.w = fmaf(w2, v2.w, acc.w);
        acc.x = fmaf(w3, v3.x, acc.x); acc.y = fmaf(w3, v3.y, acc.y);
        acc.z = fmaf(w3, v3.z, acc.z); acc.w = fmaf(w3, v3.w, acc.w);
    }
    for (; j < end; j++) {
        int s = g_srcS[j];
        float w = g_wS[j];
        float4 v = Y4[s * 32 + lane];
        acc.x = fmaf(w, v.x, acc.x); acc.y = fmaf(w, v.y, acc.y);
        acc.z = fmaf(w, v.z, acc.z); acc.w = fmaf(w, v.w, acc.w);
    }
    ((float4*)g_T)[row * 32 + lane] = acc;
}

// ---------------- GCN GEMM: h = (dis o T) @ W + b ------------------------------
// MODE 0: Y = dis * relu(h)   (conv 1, 2)
// MODE 1: X3 = h              (conv 3)
// block: 32 rows x 128 cols, 256 threads, thread tile 4x4, A in smem transposed.
template <int MODE>
__global__ void k_gemm(const float* __restrict__ W, const float* __restrict__ bias) {
    __shared__ float As[DD * 32];   // [k][row], 16 KB
    int tid = threadIdx.x;
    int r0 = blockIdx.x * 32;
    const float4* In4 = (const float4*)g_T;
    for (int idx = tid; idx < 1024; idx += 256) {
        int r = idx & 31, kk = idx >> 5;
        float ds = g_dis[r0 + r];
        float4 v = In4[(r0 + r) * 32 + kk];
        As[(kk * 4 + 0) * 32 + r] = v.x * ds;
        As[(kk * 4 + 1) * 32 + r] = v.y * ds;
        As[(kk * 4 + 2) * 32 + r] = v.z * ds;
        As[(kk * 4 + 3) * 32 + r] = v.w * ds;
    }
    __syncthreads();
    int c = tid & 31, rg = tid >> 5;
    const float4* W4 = (const float4*)W;
    const float4* As4 = (const float4*)As;
    float acc[4][4] = {};
#pragma unroll 8
    for (int k = 0; k < DD; k++) {
        float4 a = As4[k * 8 + rg];           // rows rg*4..rg*4+3 at k (broadcast)
        float4 w = __ldg(&W4[k * 32 + c]);    // cols c*4..c*4+3   (coalesced)
        acc[0][0] = fmaf(a.x, w.x, acc[0][0]); acc[0][1] = fmaf(a.x, w.y, acc[0][1]);
        acc[0][2] = fmaf(a.x, w.z, acc[0][2]); acc[0][3] = fmaf(a.x, w.w, acc[0][3]);
        acc[1][0] = fmaf(a.y, w.x, acc[1][0]); acc[1][1] = fmaf(a.y, w.y, acc[1][1]);
        acc[1][2] = fmaf(a.y, w.z, acc[1][2]); acc[1][3] = fmaf(a.y, w.w, acc[1][3]);
        acc[2][0] = fmaf(a.z, w.x, acc[2][0]); acc[2][1] = fmaf(a.z, w.y, acc[2][1]);
        acc[2][2] = fmaf(a.z, w.z, acc[2][2]); acc[2][3] = fmaf(a.z, w.w, acc[2][3]);
        acc[3][0] = fmaf(a.w, w.x, acc[3][0]); acc[3][1] = fmaf(a.w, w.y, acc[3][1]);
        acc[3][2] = fmaf(a.w, w.z, acc[3][2]); acc[3][3] = fmaf(a.w, w.w, acc[3][3]);
    }
    float4 b4 = ((const float4*)bias)[c];
    float* Out = (MODE == 0) ? g_Y : g_X3;
#pragma unroll
    for (int rr = 0; rr < 4; rr++) {
        int row = r0 + rg * 4 + rr;
        float4 o = make_float4(acc[rr][0] + b4.x, acc[rr][1] + b4.y,
                               acc[rr][2] + b4.z, acc[rr][3] + b4.w);
        if (MODE == 0) {
            float ds = g_dis[row];
            o.x = fmaxf(o.x, 0.f) * ds; o.y = fmaxf(o.y, 0.f) * ds;
            o.z = fmaxf(o.z, 0.f) * ds; o.w = fmaxf(o.w, 0.f) * ds;
        }
        ((float4*)Out)[row * 32 + c] = o;
    }
}

// ---------------- mean pool (sums + counts) ------------------------------------
__global__ void k_pool(const int* __restrict__ batch) {
    int t = blockIdx.x * blockDim.x + threadIdx.x;
    int row = t >> 5, lane = t & 31;
    if (row >= NN) return;
    int b = batch[row];
    float4 v = ((const float4*)g_X3)[row * 32 + lane];
    float* p = &g_sums[b * DD + lane * 4];
    red_add(p + 0, v.x); red_add(p + 1, v.y);
    red_add(p + 2, v.z); red_add(p + 3, v.w);
    if (lane == 0) atomicAdd(&g_cnt[b], 1.0f);
}

// ---------------- graph head: l2norm(pooled @ W_g + b_g) -----------------------
__global__ void k_ghead(const float* __restrict__ Wg, const float* __restrict__ bg,
                        float* __restrict__ out) {
    int b = blockIdx.x, j = threadIdx.x;
    __shared__ float p[DD];
    __shared__ float rbuf[4];
    __shared__ float sinv;
    float inv = 1.0f / fmaxf(g_cnt[b], 1.0f);
    p[j] = g_sums[b * DD + j] * inv;
    __syncthreads();
    float acc = bg[j];
#pragma unroll 8
    for (int k = 0; k < DD; k++) acc = fmaf(p[k], Wg[k * DD + j], acc);
    float s = acc * acc;
    for (int o = 16; o > 0; o >>= 1) s += __shfl_xor_sync(0xffffffffu, s, o);
    if ((j & 31) == 0) rbuf[j >> 5] = s;
    __syncthreads();
    if (j == 0) sinv = rsqrtf(rbuf[0] + rbuf[1] + rbuf[2] + rbuf[3]);
    __syncthreads();
    out[NBATCH * DD + b * DD + j] = acc * sinv;
}

// ---------------- image GEMM 1: q = images @ W_img + b_img ---------------------
// grid: 32 col-tiles x 8 K-splits; block 256 threads, thread tile 4 rows x 4 cols.
__global__ void k_img1(const float* __restrict__ images, const float* __restrict__ Wimg) {
    int ct = blockIdx.x & 31;
    int ks = blockIdx.x >> 5;
    int c = threadIdx.x & 31;
    int rg = threadIdx.x >> 5;       // 8 row groups x 4 rows = 32 rows
    int c0 = ct * 128 + c * 4;
    int kbase = ks * 512;
    float acc[4][4] = {};
#pragma unroll 2
    for (int k = kbase; k < kbase + 512; k += 4) {
        float4 a[4];
#pragma unroll
        for (int rr = 0; rr < 4; rr++)
            a[rr] = *(const float4*)&images[(rg * 4 + rr) * IMGD + k];
#pragma unroll
        for (int q = 0; q < 4; q++) {
            float4 w = *(const float4*)&Wimg[(size_t)(k + q) * IMGD + c0];
#pragma unroll
            for (int rr = 0; rr < 4; rr++) {
                float av = (q == 0) ? a[rr].x : (q == 1) ? a[rr].y : (q == 2) ? a[rr].z : a[rr].w;
                acc[rr][0] = fmaf(av, w.x, acc[rr][0]);
                acc[rr][1] = fmaf(av, w.y, acc[rr][1]);
                acc[rr][2] = fmaf(av, w.z, acc[rr][2]);
                acc[rr][3] = fmaf(av, w.w, acc[rr][3]);
            }
        }
    }
#pragma unroll
    for (int rr = 0; rr < 4; rr++) {
        float* p = &g_q[(rg * 4 + rr) * IMGD + c0];
        red_add(p + 0, acc[rr][0]); red_add(p + 1, acc[rr][1]);
        red_add(p + 2, acc[rr][2]); red_add(p + 3, acc[rr][3]);
    }
}

// ---------------- image head: l2norm(q @ W_i + b_i) ----------------------------
__global__ void k_img2(const float* __restrict__ Wi, const float* __restrict__ bi,
                       float* __restrict__ out) {
    int m = blockIdx.x, j = threadIdx.x;
    __shared__ float rbuf[4];
    __shared__ float sinv;
    const float* qrow = &g_q[m * IMGD];
    float acc = bi[j];
#pragma unroll 4
    for (int k = 0; k < IMGD; k += 4) {
        float4 qv = *(const float4*)&qrow[k];
        acc = fmaf(qv.x, Wi[(k + 0) * DD + j], acc);
        acc = fmaf(qv.y, Wi[(k + 1) * DD + j], acc);
        acc = fmaf(qv.z, Wi[(k + 2) * DD + j], acc);
        acc = fmaf(qv.w, Wi[(k + 3) * DD + j], acc);
    }
    float s = acc * acc;
    for (int o = 16; o > 0; o >>= 1) s += __shfl_xor_sync(0xffffffffu, s, o);
    if ((j & 31) == 0) rbuf[j >> 5] = s;
    __syncthreads();
    if (j == 0) sinv = rsqrtf(rbuf[0] + rbuf[1] + rbuf[2] + rbuf[3]);
    __syncthreads();
    out[m * DD + j] = acc * sinv;
}

// ---------------- launch --------------------------------------------------------
extern "C" void kernel_launch(void* const* d_in, const int* in_sizes, int n_in,
                              void* d_out, int out_size) {
    const float* images = (const float*)d_in[0];
    const int*   ids    = (const int*)d_in[1];
    const int*   src    = (const int*)d_in[2];
    const int*   dst    = (const int*)d_in[3];
    const float* ew     = (const float*)d_in[4];
    const int*   batch  = (const int*)d_in[5];
    const float* emb    = (const float*)d_in[6];
    const float* W_img  = (const float*)d_in[7];
    const float* b_img  = (const float*)d_in[8];
    const float* W_i    = (const float*)d_in[9];
    const float* b_i    = (const float*)d_in[10];
    const float* W1 = (const float*)d_in[11]; const float* b1 = (const float*)d_in[12];
    const float* W2 = (const float*)d_in[13]; const float* b2 = (const float*)d_in[14];
    const float* W3 = (const float*)d_in[15]; const float* b3 = (const float*)d_in[16];
    const float* W_g = (const float*)d_in[17]; const float* b_g = (const float*)d_in[18];
    float* out = (float*)d_out;

    (void)in_sizes; (void)n_in; (void)out_size;

    k_init<<<(NBATCH * IMGD + 255) / 256, 256>>>(b_img);
    k_deg_hist<<<NE / 256, 256>>>(dst, ew);
    k_scan1<<<SCAN_BLOCKS, 256>>>();
    k_scan2<<<1, 256>>>();
    k_scan3<<<SCAN_BLOCKS, 256>>>();
    k_scatter<<<NE / 256, 256>>>(src, dst, ew);
    k_gather<<<NN / 8, 256>>>(ids, emb);

    // image path
    k_img1<<<256, 256>>>(images, W_img);
    k_img2<<<NBATCH, DD>>>(W_i, b_i, out);

    // 3 GCN convs
    k_agg<<<NN / 8, 256>>>();
    k_gemm<0><<<NN / 32, 256>>>(W1, b1);
    k_agg<<<NN / 8, 256>>>();
    k_gemm<0><<<NN / 32, 256>>>(W2, b2);
    k_agg<<<NN / 8, 256>>>();
    k_gemm<1><<<NN / 32, 256>>>(W3, b3);

    k_pool<<<NN / 8, 256>>>(batch);
    k_ghead<<<NBATCH, DD>>>(W_g, b_g, out);
}